// round 10
// baseline (speedup 1.0000x reference)
#include <cuda_runtime.h>

#define BN 4096
#define DN 768
#define PN 96
#define CN 256
#define SDN 8

typedef unsigned long long u64;

__device__ __forceinline__ u64 ffma2(u64 a, u64 b, u64 c) {
    u64 d;
    asm("fma.rn.f32x2 %0, %1, %2, %3;" : "=l"(d) : "l"(a), "l"(b), "l"(c));
    return d;
}
__device__ __forceinline__ u64 fadd2(u64 a, u64 b) {
    u64 d;
    asm("add.rn.f32x2 %0, %1, %2;" : "=l"(d) : "l"(a), "l"(b));
    return d;
}
__device__ __forceinline__ u64 pack2(float lo, float hi) {
    u64 r;
    asm("mov.b64 %0, {%1, %2};" : "=l"(r) : "f"(lo), "f"(hi));
    return r;
}
__device__ __forceinline__ void unpack2(u64 v, float& lo, float& hi) {
    asm("mov.b64 {%0, %1}, %2;" : "=f"(lo), "=f"(hi) : "l"(v));
}
// Packed per-lane running min via two scalar FMNMX (alu pipe, no predicates).
__device__ __forceinline__ u64 min2(u64 a, u64 b) {
    float a0, a1, b0, b1;
    unpack2(a, a0, a1);          // free: register aliasing
    unpack2(b, b0, b1);
    return pack2(fminf(a0, b0), fminf(a1, b1));
}

// v_sq / c_sq with the reference's rounding: elementwise square (rn), then
// strictly sequential adds (rn), no fma contraction.
__device__ __forceinline__ float sumsq8(float4 lo, float4 hi) {
    float q = __fmul_rn(lo.x, lo.x);
    q = __fadd_rn(q, __fmul_rn(lo.y, lo.y));
    q = __fadd_rn(q, __fmul_rn(lo.z, lo.z));
    q = __fadd_rn(q, __fmul_rn(lo.w, lo.w));
    q = __fadd_rn(q, __fmul_rn(hi.x, hi.x));
    q = __fadd_rn(q, __fmul_rn(hi.y, hi.y));
    q = __fadd_rn(q, __fmul_rn(hi.z, hi.z));
    q = __fadd_rn(q, __fmul_rn(hi.w, hi.w));
    return q;
}

#define CHUNK 8                       // centroid-pairs per tournament chunk
#define NCHUNK (CN / 2 / CHUNK)       // 16

// Block: 128 threads, covers 256 batch vectors (2 per thread) for one partition.
// Grid: (BN/256 = 16, PN = 96).
__global__ __launch_bounds__(128) void pq_argmax_kernel(
    const float* __restrict__ vecs,
    const float* __restrict__ codebook,
    float* __restrict__ out)
{
    // Pair-interleaved codebook: row j (16 floats) = {c0_d0,c1_d0,c0_d1,c1_d1,...}
    // where c0 = 2j, c1 = 2j+1. One LDS.128 yields two packed f32x2 operands.
    __shared__ __align__(16) float cbi[CN * SDN];
    __shared__ __align__(8)  float csq[CN];   // +||c||^2, natural c order

    const int t = threadIdx.x;
    const int p = blockIdx.y;
    const float* cb = codebook + (size_t)p * CN * SDN;

    // ---- init: thread t stages centroid pair (2t, 2t+1) ----
    {
        const float4* cb4 = (const float4*)cb + t * 4;
        float4 c0lo = cb4[0], c0hi = cb4[1];   // centroid 2t,   dims 0-3 / 4-7
        float4 c1lo = cb4[2], c1hi = cb4[3];   // centroid 2t+1

        float4* row = (float4*)(cbi + t * 16);
        row[0] = make_float4(c0lo.x, c1lo.x, c0lo.y, c1lo.y);
        row[1] = make_float4(c0lo.z, c1lo.z, c0lo.w, c1lo.w);
        row[2] = make_float4(c0hi.x, c1hi.x, c0hi.y, c1hi.y);
        row[3] = make_float4(c0hi.z, c1hi.z, c0hi.w, c1hi.w);
        csq[2 * t]     = sumsq8(c0lo, c0hi);
        csq[2 * t + 1] = sumsq8(c1lo, c1hi);
    }

    // ---- load the two sub-vectors this thread owns ----
    const int b0 = blockIdx.x * 256 + t;
    const int b1 = b0 + 128;
    const float4* va4 = (const float4*)(vecs + (size_t)b0 * DN + p * SDN);
    const float4* vb4 = (const float4*)(vecs + (size_t)b1 * DN + p * SDN);
    float4 a0 = va4[0], a1 = va4[1];
    float4 e0 = vb4[0], e1 = vb4[1];

    u64 wa[8], wb[8];
    wa[0] = pack2(a0.x, a0.x); wa[1] = pack2(a0.y, a0.y);
    wa[2] = pack2(a0.z, a0.z); wa[3] = pack2(a0.w, a0.w);
    wa[4] = pack2(a1.x, a1.x); wa[5] = pack2(a1.y, a1.y);
    wa[6] = pack2(a1.z, a1.z); wa[7] = pack2(a1.w, a1.w);
    wb[0] = pack2(e0.x, e0.x); wb[1] = pack2(e0.y, e0.y);
    wb[2] = pack2(e0.z, e0.z); wb[3] = pack2(e0.w, e0.w);
    wb[4] = pack2(e1.x, e1.x); wb[5] = pack2(e1.y, e1.y);
    wb[6] = pack2(e1.z, e1.z); wb[7] = pack2(e1.w, e1.w);

    const float vsA = sumsq8(a0, a1);
    const float vsB = sumsq8(e0, e1);
    const u64 vsqA = pack2(vsA, vsA);
    const u64 vsqB = pack2(vsB, vsB);

    __syncthreads();

    // 2*vc is exact in fp32 (exponent bump), so the reference's
    //   m = rn(2*vc); d = rn(v_sq - m)
    // equals the single fma  d = rn(v_sq - 2*vc) = fma(vc, -2, v_sq).
    const u64 NEG2 = pack2(-2.0f, -2.0f);
    const float INF = 3.402823466e+38f;
    const u64 INF2 = pack2(INF, INF);
    const ulonglong2* rows = (const ulonglong2*)cbi;
    const u64* nq = (const u64*)csq;

    float bestA = INF, bestB = INF;
    int bkA = 0, bkB = 0;             // winning CHUNK index per b

    for (int k = 0; k < NCHUNK; ++k) {
        u64 cmA = INF2, cmB = INF2;   // packed per-lane chunk minima

        #pragma unroll
        for (int jj = 0; jj < CHUNK; ++jj) {
            const int j = k * CHUNK + jj;
            ulonglong2 r0 = rows[j * 4 + 0];   // d0,d1 ({c_even, c_odd} each)
            ulonglong2 r1 = rows[j * 4 + 1];   // d2,d3
            ulonglong2 r2 = rows[j * 4 + 2];   // d4,d5
            ulonglong2 r3 = rows[j * 4 + 3];   // d6,d7
            u64 q = nq[j];                     // {csq_even, csq_odd}

            u64 accA = 0ULL, accB = 0ULL;
            accA = ffma2(wa[0], r0.x, accA);  accB = ffma2(wb[0], r0.x, accB);
            accA = ffma2(wa[1], r0.y, accA);  accB = ffma2(wb[1], r0.y, accB);
            accA = ffma2(wa[2], r1.x, accA);  accB = ffma2(wb[2], r1.x, accB);
            accA = ffma2(wa[3], r1.y, accA);  accB = ffma2(wb[3], r1.y, accB);
            accA = ffma2(wa[4], r2.x, accA);  accB = ffma2(wb[4], r2.x, accB);
            accA = ffma2(wa[5], r2.y, accA);  accB = ffma2(wb[5], r2.y, accB);
            accA = ffma2(wa[6], r3.x, accA);  accB = ffma2(wb[6], r3.x, accB);
            accA = ffma2(wa[7], r3.y, accA);  accB = ffma2(wb[7], r3.y, accB);

            u64 sA = fadd2(ffma2(accA, NEG2, vsqA), q);
            u64 sB = fadd2(ffma2(accB, NEG2, vsqB), q);

            cmA = min2(cmA, sA);      // 2x FMNMX, alu pipe, no predicates
            cmB = min2(cmB, sB);
        }

        // Chunk boundary: one scalar compare per b. Strict '<' keeps the
        // earliest chunk on exact ties.
        float c0, c1;
        unpack2(cmA, c0, c1);
        { float lv = fminf(c0, c1); bool m = lv < bestA;
          bestA = fminf(bestA, lv); if (m) bkA = k; }
        unpack2(cmB, c0, c1);
        { float lv = fminf(c0, c1); bool m = lv < bestB;
          bestB = fminf(bestB, lv); if (m) bkB = k; }
    }

    // ---- epilogue: recompute ONLY the winning chunk per b with the identical
    // op sequence (bitwise-same scores). Strict '<' over pairs keeps the
    // earliest pair; strict s1<s0 keeps the even lane on ties — matching
    // jnp.argmax first-index on proba = -s.
    const u64* wsel[2] = { wa, wb };
    const u64  vsel[2] = { vsqA, vsqB };
    const int  ksel[2] = { bkA, bkB };
    const int  bsel[2] = { b0, b1 };

    #pragma unroll
    for (int g = 0; g < 2; ++g) {
        const u64* w = wsel[g];
        const u64 vsq = vsel[g];
        const int kw = ksel[g];

        float bpv = INF;
        int bj = kw * CHUNK, lane = 0;
        #pragma unroll
        for (int jj = 0; jj < CHUNK; ++jj) {
            const int j = kw * CHUNK + jj;
            ulonglong2 r0 = rows[j * 4 + 0], r1 = rows[j * 4 + 1];
            ulonglong2 r2 = rows[j * 4 + 2], r3 = rows[j * 4 + 3];
            u64 q = nq[j];
            u64 acc = 0ULL;
            acc = ffma2(w[0], r0.x, acc); acc = ffma2(w[1], r0.y, acc);
            acc = ffma2(w[2], r1.x, acc); acc = ffma2(w[3], r1.y, acc);
            acc = ffma2(w[4], r2.x, acc); acc = ffma2(w[5], r2.y, acc);
            acc = ffma2(w[6], r3.x, acc); acc = ffma2(w[7], r3.y, acc);
            u64 s = fadd2(ffma2(acc, NEG2, vsq), q);
            float s0, s1; unpack2(s, s0, s1);
            float lv = fminf(s0, s1);
            int   ll = (s1 < s0) ? 1 : 0;
            if (lv < bpv) { bpv = lv; bj = j; lane = ll; }
        }

        int base = bj * 16 + lane;
        float4 o0 = make_float4(cbi[base],      cbi[base + 2],
                                cbi[base + 4],  cbi[base + 6]);
        float4 o1 = make_float4(cbi[base + 8],  cbi[base + 10],
                                cbi[base + 12], cbi[base + 14]);
        float4* o = (float4*)(out + (size_t)bsel[g] * DN + p * SDN);
        o[0] = o0; o[1] = o1;
    }
}

extern "C" void kernel_launch(void* const* d_in, const int* in_sizes, int n_in,
                              void* d_out, int out_size) {
    const float* vecs     = (const float*)d_in[0];
    const float* codebook = (const float*)d_in[1];
    // Defensive: inputs are (vecs: B*D = 3145728, codebook: P*C*SD = 196608)
    if (n_in >= 2 && in_sizes[0] == PN * CN * SDN && in_sizes[1] == BN * DN) {
        const float* tmp = vecs; vecs = codebook; codebook = tmp;
    }
    float* out = (float*)d_out;
    dim3 grid(BN / 256, PN);
    pq_argmax_kernel<<<grid, 128>>>(vecs, codebook, out);
}

// round 11
// speedup vs baseline: 1.2196x; 1.2196x over previous
#include <cuda_runtime.h>

#define BN 4096
#define DN 768
#define PN 96
#define CN 256
#define SDN 8

typedef unsigned long long u64;

__device__ __forceinline__ u64 ffma2(u64 a, u64 b, u64 c) {
    u64 d;
    asm("fma.rn.f32x2 %0, %1, %2, %3;" : "=l"(d) : "l"(a), "l"(b), "l"(c));
    return d;
}
__device__ __forceinline__ u64 fadd2(u64 a, u64 b) {
    u64 d;
    asm("add.rn.f32x2 %0, %1, %2;" : "=l"(d) : "l"(a), "l"(b));
    return d;
}
__device__ __forceinline__ u64 pack2(float lo, float hi) {
    u64 r;
    asm("mov.b64 %0, {%1, %2};" : "=l"(r) : "f"(lo), "f"(hi));
    return r;
}
__device__ __forceinline__ void unpack2(u64 v, float& lo, float& hi) {
    asm("mov.b64 {%0, %1}, %2;" : "=f"(lo), "=f"(hi) : "l"(v));
}

// v_sq / c_sq with the reference's rounding: elementwise square (rn), then
// strictly sequential adds (rn), no fma contraction.
__device__ __forceinline__ float sumsq8(float4 lo, float4 hi) {
    float q = __fmul_rn(lo.x, lo.x);
    q = __fadd_rn(q, __fmul_rn(lo.y, lo.y));
    q = __fadd_rn(q, __fmul_rn(lo.z, lo.z));
    q = __fadd_rn(q, __fmul_rn(lo.w, lo.w));
    q = __fadd_rn(q, __fmul_rn(hi.x, hi.x));
    q = __fadd_rn(q, __fmul_rn(hi.y, hi.y));
    q = __fadd_rn(q, __fmul_rn(hi.z, hi.z));
    q = __fadd_rn(q, __fmul_rn(hi.w, hi.w));
    return q;
}

// Block: 128 threads, 1 batch vector per thread, one partition per block.
// Grid: (BN/128 = 32, PN = 96) = 3072 blocks.
__global__ __launch_bounds__(128, 12) void pq_argmax_kernel(
    const float* __restrict__ vecs,
    const float* __restrict__ codebook,
    float* __restrict__ out)
{
    // Pair-interleaved codebook: row j (16 floats) = {c0_d0,c1_d0,c0_d1,c1_d1,...}
    // where c0 = 2j, c1 = 2j+1. One LDS.128 yields two packed f32x2 operands.
    __shared__ __align__(16) float cbi[CN * SDN];
    __shared__ __align__(8)  float csq[CN];   // +||c||^2, natural c order

    const int t = threadIdx.x;
    const int p = blockIdx.y;
    const float* cb = codebook + (size_t)p * CN * SDN;

    // ---- init: thread t stages centroid pair (2t, 2t+1) ----
    {
        const float4* cb4 = (const float4*)cb + t * 4;
        float4 c0lo = cb4[0], c0hi = cb4[1];   // centroid 2t,   dims 0-3 / 4-7
        float4 c1lo = cb4[2], c1hi = cb4[3];   // centroid 2t+1

        float4* row = (float4*)(cbi + t * 16);
        row[0] = make_float4(c0lo.x, c1lo.x, c0lo.y, c1lo.y);
        row[1] = make_float4(c0lo.z, c1lo.z, c0lo.w, c1lo.w);
        row[2] = make_float4(c0hi.x, c1hi.x, c0hi.y, c1hi.y);
        row[3] = make_float4(c0hi.z, c1hi.z, c0hi.w, c1hi.w);
        csq[2 * t]     = sumsq8(c0lo, c0hi);
        csq[2 * t + 1] = sumsq8(c1lo, c1hi);
    }

    // ---- load the sub-vector this thread owns ----
    const int b = blockIdx.x * 128 + t;
    const float4* v4 = (const float4*)(vecs + (size_t)b * DN + p * SDN);
    float4 a0 = v4[0], a1 = v4[1];

    u64 w[8];
    w[0] = pack2(a0.x, a0.x); w[1] = pack2(a0.y, a0.y);
    w[2] = pack2(a0.z, a0.z); w[3] = pack2(a0.w, a0.w);
    w[4] = pack2(a1.x, a1.x); w[5] = pack2(a1.y, a1.y);
    w[6] = pack2(a1.z, a1.z); w[7] = pack2(a1.w, a1.w);

    const float vs = sumsq8(a0, a1);
    const u64 vsq = pack2(vs, vs);

    __syncthreads();

    // 2*vc is exact in fp32 (exponent bump), so the reference's
    //   m = rn(2*vc); d = rn(v_sq - m)
    // equals the single fma  d = rn(v_sq - 2*vc) = fma(vc, -2, v_sq).
    const u64 NEG2 = pack2(-2.0f, -2.0f);
    const ulonglong2* rows = (const ulonglong2*)cbi;
    const u64* nq = (const u64*)csq;

    float best = 3.402823466e+38f;
    int bj = 0;                        // winning centroid-PAIR index

    #pragma unroll 4
    for (int j = 0; j < CN / 2; ++j) {
        ulonglong2 r0 = rows[j * 4 + 0];   // d0,d1 (each u64 = {c_even, c_odd})
        ulonglong2 r1 = rows[j * 4 + 1];   // d2,d3
        ulonglong2 r2 = rows[j * 4 + 2];   // d4,d5
        ulonglong2 r3 = rows[j * 4 + 3];   // d6,d7
        u64 q = nq[j];                     // {csq_even, csq_odd}

        u64 acc = 0ULL;                    // {0.f, 0.f}
        acc = ffma2(w[0], r0.x, acc);
        acc = ffma2(w[1], r0.y, acc);
        acc = ffma2(w[2], r1.x, acc);
        acc = ffma2(w[3], r1.y, acc);
        acc = ffma2(w[4], r2.x, acc);
        acc = ffma2(w[5], r2.y, acc);
        acc = ffma2(w[6], r3.x, acc);
        acc = ffma2(w[7], r3.y, acc);

        u64 s = fadd2(ffma2(acc, NEG2, vsq), q);

        float s0, s1;
        unpack2(s, s0, s1);

        // Index-free tournament: strict '<' on the pair-min keeps the earliest
        // pair on exact ties (matches jnp.argmax first-index on proba = -s).
        float lv = fminf(s0, s1);
        bool m = lv < best;
        best = fminf(best, lv);
        if (m) bj = j;
    }

    // ---- epilogue: recompute ONLY the winning pair to resolve even/odd lane.
    // Identical op sequence => bitwise-identical scores. Even lane wins ties
    // (strict s1 < s0), matching first-index argmax.
    int bi;
    {
        ulonglong2 r0 = rows[bj * 4 + 0], r1 = rows[bj * 4 + 1];
        ulonglong2 r2 = rows[bj * 4 + 2], r3 = rows[bj * 4 + 3];
        u64 q = nq[bj];
        u64 acc = 0ULL;
        acc = ffma2(w[0], r0.x, acc); acc = ffma2(w[1], r0.y, acc);
        acc = ffma2(w[2], r1.x, acc); acc = ffma2(w[3], r1.y, acc);
        acc = ffma2(w[4], r2.x, acc); acc = ffma2(w[5], r2.y, acc);
        acc = ffma2(w[6], r3.x, acc); acc = ffma2(w[7], r3.y, acc);
        u64 s = fadd2(ffma2(acc, NEG2, vsq), q);
        float s0, s1; unpack2(s, s0, s1);
        bi = 2 * bj + ((s1 < s0) ? 1 : 0);
    }

    // ---- emit winning centroid row (copied exactly from staged codebook) ----
    {
        int base = (bi >> 1) * 16 + (bi & 1);
        float4 o0 = make_float4(cbi[base],      cbi[base + 2],
                                cbi[base + 4],  cbi[base + 6]);
        float4 o1 = make_float4(cbi[base + 8],  cbi[base + 10],
                                cbi[base + 12], cbi[base + 14]);
        float4* o = (float4*)(out + (size_t)b * DN + p * SDN);
        o[0] = o0; o[1] = o1;
    }
}

extern "C" void kernel_launch(void* const* d_in, const int* in_sizes, int n_in,
                              void* d_out, int out_size) {
    const float* vecs     = (const float*)d_in[0];
    const float* codebook = (const float*)d_in[1];
    // Defensive: inputs are (vecs: B*D = 3145728, codebook: P*C*SD = 196608)
    if (n_in >= 2 && in_sizes[0] == PN * CN * SDN && in_sizes[1] == BN * DN) {
        const float* tmp = vecs; vecs = codebook; codebook = tmp;
    }
    float* out = (float*)d_out;
    dim3 grid(BN / 128, PN);
    pq_argmax_kernel<<<grid, 128>>>(vecs, codebook, out);
}

// round 13
// speedup vs baseline: 1.2731x; 1.0439x over previous
#include <cuda_runtime.h>

#define BN 4096
#define DN 768
#define PN 96
#define CN 256
#define SDN 8

typedef unsigned long long u64;

__device__ __forceinline__ u64 ffma2(u64 a, u64 b, u64 c) {
    u64 d;
    asm("fma.rn.f32x2 %0, %1, %2, %3;" : "=l"(d) : "l"(a), "l"(b), "l"(c));
    return d;
}
__device__ __forceinline__ u64 fadd2(u64 a, u64 b) {
    u64 d;
    asm("add.rn.f32x2 %0, %1, %2;" : "=l"(d) : "l"(a), "l"(b));
    return d;
}
__device__ __forceinline__ u64 pack2(float lo, float hi) {
    u64 r;
    asm("mov.b64 %0, {%1, %2};" : "=l"(r) : "f"(lo), "f"(hi));
    return r;
}
__device__ __forceinline__ void unpack2(u64 v, float& lo, float& hi) {
    asm("mov.b64 {%0, %1}, %2;" : "=f"(lo), "=f"(hi) : "l"(v));
}

// v_sq / c_sq with the reference's rounding: elementwise square (rn), then
// strictly sequential adds (rn), no fma contraction.
__device__ __forceinline__ float sumsq8(float4 lo, float4 hi) {
    float q = __fmul_rn(lo.x, lo.x);
    q = __fadd_rn(q, __fmul_rn(lo.y, lo.y));
    q = __fadd_rn(q, __fmul_rn(lo.z, lo.z));
    q = __fadd_rn(q, __fmul_rn(lo.w, lo.w));
    q = __fadd_rn(q, __fmul_rn(hi.x, hi.x));
    q = __fadd_rn(q, __fmul_rn(hi.y, hi.y));
    q = __fadd_rn(q, __fmul_rn(hi.z, hi.z));
    q = __fadd_rn(q, __fmul_rn(hi.w, hi.w));
    return q;
}

// Block: 64 threads, 2 batch vectors per thread (128 b/block), one partition.
// Grid: (BN/128 = 32, PN = 96) = 3072 blocks of 2 warps -> ~42 warps/SM
// resident (vs 28 with 128-thread blocks), same LDS/work as the 57.9us best.
__global__ __launch_bounds__(64, 21) void pq_argmax_kernel(
    const float* __restrict__ vecs,
    const float* __restrict__ codebook,
    float* __restrict__ out)
{
    // Pair-interleaved codebook: row j (16 floats) = {c0_d0,c1_d0,c0_d1,c1_d1,...}
    // where c0 = 2j, c1 = 2j+1. One LDS.128 yields two packed f32x2 operands.
    __shared__ __align__(16) float cbi[CN * SDN];
    __shared__ __align__(8)  float csq[CN];   // +||c||^2, natural c order

    const int t = threadIdx.x;
    const int p = blockIdx.y;
    const float* cb = codebook + (size_t)p * CN * SDN;

    // ---- init: thread t stages centroid pairs 2t and 2t+1 (128 pairs total) ----
    #pragma unroll
    for (int i = 0; i < 2; ++i) {
        const int j2 = 2 * t + i;                 // pair index, 0..127
        const float4* cb4 = (const float4*)cb + j2 * 4;
        float4 c0lo = cb4[0], c0hi = cb4[1];      // centroid 2*j2
        float4 c1lo = cb4[2], c1hi = cb4[3];      // centroid 2*j2+1

        float4* row = (float4*)(cbi + j2 * 16);
        row[0] = make_float4(c0lo.x, c1lo.x, c0lo.y, c1lo.y);
        row[1] = make_float4(c0lo.z, c1lo.z, c0lo.w, c1lo.w);
        row[2] = make_float4(c0hi.x, c1hi.x, c0hi.y, c1hi.y);
        row[3] = make_float4(c0hi.z, c1hi.z, c0hi.w, c1hi.w);
        csq[2 * j2]     = sumsq8(c0lo, c0hi);
        csq[2 * j2 + 1] = sumsq8(c1lo, c1hi);
    }

    // ---- load the two sub-vectors this thread owns ----
    const int b0 = blockIdx.x * 128 + t;
    const int b1 = b0 + 64;
    const float4* va4 = (const float4*)(vecs + (size_t)b0 * DN + p * SDN);
    const float4* vb4 = (const float4*)(vecs + (size_t)b1 * DN + p * SDN);
    float4 a0 = va4[0], a1 = va4[1];
    float4 e0 = vb4[0], e1 = vb4[1];

    u64 wa[8], wb[8];
    wa[0] = pack2(a0.x, a0.x); wa[1] = pack2(a0.y, a0.y);
    wa[2] = pack2(a0.z, a0.z); wa[3] = pack2(a0.w, a0.w);
    wa[4] = pack2(a1.x, a1.x); wa[5] = pack2(a1.y, a1.y);
    wa[6] = pack2(a1.z, a1.z); wa[7] = pack2(a1.w, a1.w);
    wb[0] = pack2(e0.x, e0.x); wb[1] = pack2(e0.y, e0.y);
    wb[2] = pack2(e0.z, e0.z); wb[3] = pack2(e0.w, e0.w);
    wb[4] = pack2(e1.x, e1.x); wb[5] = pack2(e1.y, e1.y);
    wb[6] = pack2(e1.z, e1.z); wb[7] = pack2(e1.w, e1.w);

    const float vsA = sumsq8(a0, a1);
    const float vsB = sumsq8(e0, e1);
    const u64 vsqA = pack2(vsA, vsA);
    const u64 vsqB = pack2(vsB, vsB);

    __syncthreads();

    // 2*vc is exact in fp32 (exponent bump), so the reference's
    //   m = rn(2*vc); d = rn(v_sq - m)
    // equals the single fma  d = rn(v_sq - 2*vc) = fma(vc, -2, v_sq).
    const u64 NEG2 = pack2(-2.0f, -2.0f);
    const ulonglong2* rows = (const ulonglong2*)cbi;
    const u64* nq = (const u64*)csq;

    float bestA = 3.402823466e+38f, bestB = 3.402823466e+38f;
    int bjA = 0, bjB = 0;   // winning centroid-PAIR index; lane resolved later

    #pragma unroll 4
    for (int j = 0; j < CN / 2; ++j) {
        ulonglong2 r0 = rows[j * 4 + 0];   // d0, d1 (each u64 = {c_even, c_odd})
        ulonglong2 r1 = rows[j * 4 + 1];   // d2, d3
        ulonglong2 r2 = rows[j * 4 + 2];   // d4, d5
        ulonglong2 r3 = rows[j * 4 + 3];   // d6, d7
        u64 q = nq[j];                     // {csq_even, csq_odd}

        u64 accA = 0ULL, accB = 0ULL;      // {0.f, 0.f}
        accA = ffma2(wa[0], r0.x, accA);  accB = ffma2(wb[0], r0.x, accB);
        accA = ffma2(wa[1], r0.y, accA);  accB = ffma2(wb[1], r0.y, accB);
        accA = ffma2(wa[2], r1.x, accA);  accB = ffma2(wb[2], r1.x, accB);
        accA = ffma2(wa[3], r1.y, accA);  accB = ffma2(wb[3], r1.y, accB);
        accA = ffma2(wa[4], r2.x, accA);  accB = ffma2(wb[4], r2.x, accB);
        accA = ffma2(wa[5], r2.y, accA);  accB = ffma2(wb[5], r2.y, accB);
        accA = ffma2(wa[6], r3.x, accA);  accB = ffma2(wb[6], r3.x, accB);
        accA = ffma2(wa[7], r3.y, accA);  accB = ffma2(wb[7], r3.y, accB);

        u64 sA = fadd2(ffma2(accA, NEG2, vsqA), q);
        u64 sB = fadd2(ffma2(accB, NEG2, vsqB), q);

        float s0, s1;
        unpack2(sA, s0, s1);
        // Index-free tournament: strict '<' on the pair-min keeps the earliest
        // pair on exact ties (matches jnp.argmax first-index on proba = -s).
        { float lv = fminf(s0, s1); bool m = lv < bestA;
          bestA = fminf(bestA, lv); if (m) bjA = j; }
        unpack2(sB, s0, s1);
        { float lv = fminf(s0, s1); bool m = lv < bestB;
          bestB = fminf(bestB, lv); if (m) bjB = j; }
    }

    // ---- epilogue: recompute ONLY the winning pair to resolve even/odd lane.
    // Identical op sequence => bitwise-identical scores. Even lane wins ties
    // (strict s1 < s0), matching first-index argmax.
    const u64* wsel[2] = { wa, wb };
    const u64  vsel[2] = { vsqA, vsqB };
    const int  jsel[2] = { bjA, bjB };
    const int  bsel[2] = { b0, b1 };

    #pragma unroll
    for (int g = 0; g < 2; ++g) {
        const u64* w = wsel[g];
        const int bj = jsel[g];
        ulonglong2 r0 = rows[bj * 4 + 0], r1 = rows[bj * 4 + 1];
        ulonglong2 r2 = rows[bj * 4 + 2], r3 = rows[bj * 4 + 3];
        u64 q = nq[bj];
        u64 acc = 0ULL;
        acc = ffma2(w[0], r0.x, acc); acc = ffma2(w[1], r0.y, acc);
        acc = ffma2(w[2], r1.x, acc); acc = ffma2(w[3], r1.y, acc);
        acc = ffma2(w[4], r2.x, acc); acc = ffma2(w[5], r2.y, acc);
        acc = ffma2(w[6], r3.x, acc); acc = ffma2(w[7], r3.y, acc);
        u64 s = fadd2(ffma2(acc, NEG2, vsel[g]), q);
        float s0, s1; unpack2(s, s0, s1);
        int lane = (s1 < s0) ? 1 : 0;
        int base = bj * 16 + lane;

        float4 o0 = make_float4(cbi[base],      cbi[base + 2],
                                cbi[base + 4],  cbi[base + 6]);
        float4 o1 = make_float4(cbi[base + 8],  cbi[base + 10],
                                cbi[base + 12], cbi[base + 14]);
        float4* o = (float4*)(out + (size_t)bsel[g] * DN + p * SDN);
        o[0] = o0; o[1] = o1;
    }
}

extern "C" void kernel_launch(void* const* d_in, const int* in_sizes, int n_in,
                              void* d_out, int out_size) {
    const float* vecs     = (const float*)d_in[0];
    const float* codebook = (const float*)d_in[1];
    // Defensive: inputs are (vecs: B*D = 3145728, codebook: P*C*SD = 196608)
    if (n_in >= 2 && in_sizes[0] == PN * CN * SDN && in_sizes[1] == BN * DN) {
        const float* tmp = vecs; vecs = codebook; codebook = tmp;
    }
    float* out = (float*)d_out;
    dim3 grid(BN / 128, PN);
    pq_argmax_kernel<<<grid, 64>>>(vecs, codebook, out);
}

// round 14
// speedup vs baseline: 1.3884x; 1.0905x over previous
#include <cuda_runtime.h>

#define BN 4096
#define DN 768
#define PN 96
#define CN 256
#define SDN 8

typedef unsigned long long u64;

__device__ __forceinline__ u64 ffma2(u64 a, u64 b, u64 c) {
    u64 d;
    asm("fma.rn.f32x2 %0, %1, %2, %3;" : "=l"(d) : "l"(a), "l"(b), "l"(c));
    return d;
}
__device__ __forceinline__ u64 fadd2(u64 a, u64 b) {
    u64 d;
    asm("add.rn.f32x2 %0, %1, %2;" : "=l"(d) : "l"(a), "l"(b));
    return d;
}
__device__ __forceinline__ u64 pack2(float lo, float hi) {
    u64 r;
    asm("mov.b64 %0, {%1, %2};" : "=l"(r) : "f"(lo), "f"(hi));
    return r;
}
__device__ __forceinline__ void unpack2(u64 v, float& lo, float& hi) {
    asm("mov.b64 {%0, %1}, %2;" : "=f"(lo), "=f"(hi) : "l"(v));
}

// v_sq / c_sq with the reference's rounding: elementwise square (rn), then
// strictly sequential adds (rn), no fma contraction.
__device__ __forceinline__ float sumsq8(float4 lo, float4 hi) {
    float q = __fmul_rn(lo.x, lo.x);
    q = __fadd_rn(q, __fmul_rn(lo.y, lo.y));
    q = __fadd_rn(q, __fmul_rn(lo.z, lo.z));
    q = __fadd_rn(q, __fmul_rn(lo.w, lo.w));
    q = __fadd_rn(q, __fmul_rn(hi.x, hi.x));
    q = __fadd_rn(q, __fmul_rn(hi.y, hi.y));
    q = __fadd_rn(q, __fmul_rn(hi.z, hi.z));
    q = __fadd_rn(q, __fmul_rn(hi.w, hi.w));
    return q;
}

// Block: 64 threads, 4 batch vectors per thread (256 b/block), one partition.
// Grid: (BN/256 = 16, PN = 96) = 1536 blocks of 2 warps.
// Software-pipelined j-loop: pair j+1's smem rows are loaded before pair j's
// fma block, covering the 29-cycle LDS latency with in-warp ILP.
__global__ __launch_bounds__(64, 10) void pq_argmax_kernel(
    const float* __restrict__ vecs,
    const float* __restrict__ codebook,
    float* __restrict__ out)
{
    // Pair-interleaved codebook: row j (16 floats) = {c0_d0,c1_d0,c0_d1,c1_d1,...}
    // where c0 = 2j, c1 = 2j+1. One LDS.128 yields two packed f32x2 operands.
    // +16 floats / +2 csq padding so the pipelined j+1 read needs no branch.
    __shared__ __align__(16) float cbi[CN * SDN + 16];
    __shared__ __align__(8)  float csq[CN + 2];   // +||c||^2

    const int t = threadIdx.x;
    const int p = blockIdx.y;
    const float* cb = codebook + (size_t)p * CN * SDN;

    // ---- init: thread t stages centroid pairs 2t, 2t+1 (128 pairs total) ----
    #pragma unroll
    for (int i = 0; i < 2; ++i) {
        const int j2 = 2 * t + i;                 // pair index, 0..127
        const float4* cb4 = (const float4*)cb + j2 * 4;
        float4 c0lo = cb4[0], c0hi = cb4[1];      // centroid 2*j2
        float4 c1lo = cb4[2], c1hi = cb4[3];      // centroid 2*j2+1

        float4* row = (float4*)(cbi + j2 * 16);
        row[0] = make_float4(c0lo.x, c1lo.x, c0lo.y, c1lo.y);
        row[1] = make_float4(c0lo.z, c1lo.z, c0lo.w, c1lo.w);
        row[2] = make_float4(c0hi.x, c1hi.x, c0hi.y, c1hi.y);
        row[3] = make_float4(c0hi.z, c1hi.z, c0hi.w, c1hi.w);
        csq[2 * j2]     = sumsq8(c0lo, c0hi);
        csq[2 * j2 + 1] = sumsq8(c1lo, c1hi);
    }
    if (t == 0) {            // zero the pipeline pad (values never win; finite)
        float4* pad = (float4*)(cbi + CN * SDN);
        pad[0] = pad[1] = pad[2] = pad[3] = make_float4(0.f, 0.f, 0.f, 0.f);
        csq[CN] = csq[CN + 1] = 3.0e+38f;
    }

    // ---- load the four sub-vectors this thread owns ----
    const int b0 = blockIdx.x * 256 + t;          // +0, +64, +128, +192
    const float4* v0 = (const float4*)(vecs + (size_t)b0 * DN + p * SDN);
    const float4* v1 = (const float4*)(vecs + (size_t)(b0 + 64) * DN + p * SDN);
    const float4* v2 = (const float4*)(vecs + (size_t)(b0 + 128) * DN + p * SDN);
    const float4* v3 = (const float4*)(vecs + (size_t)(b0 + 192) * DN + p * SDN);
    float4 a0 = v0[0], a1 = v0[1];
    float4 e0 = v1[0], e1 = v1[1];
    float4 f0 = v2[0], f1 = v2[1];
    float4 g0 = v3[0], g1 = v3[1];

    u64 wa[8], wb[8], wc[8], wd[8];
    wa[0] = pack2(a0.x, a0.x); wa[1] = pack2(a0.y, a0.y);
    wa[2] = pack2(a0.z, a0.z); wa[3] = pack2(a0.w, a0.w);
    wa[4] = pack2(a1.x, a1.x); wa[5] = pack2(a1.y, a1.y);
    wa[6] = pack2(a1.z, a1.z); wa[7] = pack2(a1.w, a1.w);
    wb[0] = pack2(e0.x, e0.x); wb[1] = pack2(e0.y, e0.y);
    wb[2] = pack2(e0.z, e0.z); wb[3] = pack2(e0.w, e0.w);
    wb[4] = pack2(e1.x, e1.x); wb[5] = pack2(e1.y, e1.y);
    wb[6] = pack2(e1.z, e1.z); wb[7] = pack2(e1.w, e1.w);
    wc[0] = pack2(f0.x, f0.x); wc[1] = pack2(f0.y, f0.y);
    wc[2] = pack2(f0.z, f0.z); wc[3] = pack2(f0.w, f0.w);
    wc[4] = pack2(f1.x, f1.x); wc[5] = pack2(f1.y, f1.y);
    wc[6] = pack2(f1.z, f1.z); wc[7] = pack2(f1.w, f1.w);
    wd[0] = pack2(g0.x, g0.x); wd[1] = pack2(g0.y, g0.y);
    wd[2] = pack2(g0.z, g0.z); wd[3] = pack2(g0.w, g0.w);
    wd[4] = pack2(g1.x, g1.x); wd[5] = pack2(g1.y, g1.y);
    wd[6] = pack2(g1.z, g1.z); wd[7] = pack2(g1.w, g1.w);

    const float vA = sumsq8(a0, a1), vB = sumsq8(e0, e1);
    const float vC = sumsq8(f0, f1), vD = sumsq8(g0, g1);
    const u64 vsqA = pack2(vA, vA), vsqB = pack2(vB, vB);
    const u64 vsqC = pack2(vC, vC), vsqD = pack2(vD, vD);

    __syncthreads();

    // 2*vc is exact in fp32 (exponent bump), so the reference's
    //   m = rn(2*vc); d = rn(v_sq - m)
    // equals the single fma  d = rn(v_sq - 2*vc) = fma(vc, -2, v_sq).
    const u64 NEG2 = pack2(-2.0f, -2.0f);
    const ulonglong2* rows = (const ulonglong2*)cbi;
    const u64* nq = (const u64*)csq;

    float bestA = 3.402823466e+38f, bestB = 3.402823466e+38f;
    float bestC = 3.402823466e+38f, bestD = 3.402823466e+38f;
    int bjA = 0, bjB = 0, bjC = 0, bjD = 0;   // winning PAIR index

    // pipeline prologue: load pair 0
    ulonglong2 r0 = rows[0], r1 = rows[1], r2 = rows[2], r3 = rows[3];
    u64 q = nq[0];

    #pragma unroll 2
    for (int j = 0; j < CN / 2; ++j) {
        // prefetch pair j+1 (pad makes j=127 safe)
        ulonglong2 n0 = rows[(j + 1) * 4 + 0];
        ulonglong2 n1 = rows[(j + 1) * 4 + 1];
        ulonglong2 n2 = rows[(j + 1) * 4 + 2];
        ulonglong2 n3 = rows[(j + 1) * 4 + 3];
        u64 qn = nq[j + 1];

        u64 accA = 0ULL, accB = 0ULL, accC = 0ULL, accD = 0ULL;
        accA = ffma2(wa[0], r0.x, accA); accB = ffma2(wb[0], r0.x, accB);
        accC = ffma2(wc[0], r0.x, accC); accD = ffma2(wd[0], r0.x, accD);
        accA = ffma2(wa[1], r0.y, accA); accB = ffma2(wb[1], r0.y, accB);
        accC = ffma2(wc[1], r0.y, accC); accD = ffma2(wd[1], r0.y, accD);
        accA = ffma2(wa[2], r1.x, accA); accB = ffma2(wb[2], r1.x, accB);
        accC = ffma2(wc[2], r1.x, accC); accD = ffma2(wd[2], r1.x, accD);
        accA = ffma2(wa[3], r1.y, accA); accB = ffma2(wb[3], r1.y, accB);
        accC = ffma2(wc[3], r1.y, accC); accD = ffma2(wd[3], r1.y, accD);
        accA = ffma2(wa[4], r2.x, accA); accB = ffma2(wb[4], r2.x, accB);
        accC = ffma2(wc[4], r2.x, accC); accD = ffma2(wd[4], r2.x, accD);
        accA = ffma2(wa[5], r2.y, accA); accB = ffma2(wb[5], r2.y, accB);
        accC = ffma2(wc[5], r2.y, accC); accD = ffma2(wd[5], r2.y, accD);
        accA = ffma2(wa[6], r3.x, accA); accB = ffma2(wb[6], r3.x, accB);
        accC = ffma2(wc[6], r3.x, accC); accD = ffma2(wd[6], r3.x, accD);
        accA = ffma2(wa[7], r3.y, accA); accB = ffma2(wb[7], r3.y, accB);
        accC = ffma2(wc[7], r3.y, accC); accD = ffma2(wd[7], r3.y, accD);

        u64 sA = fadd2(ffma2(accA, NEG2, vsqA), q);
        u64 sB = fadd2(ffma2(accB, NEG2, vsqB), q);
        u64 sC = fadd2(ffma2(accC, NEG2, vsqC), q);
        u64 sD = fadd2(ffma2(accD, NEG2, vsqD), q);

        float s0, s1;
        // Index-free tournament: strict '<' on the pair-min keeps the earliest
        // pair on exact ties (matches jnp.argmax first-index on proba = -s).
        unpack2(sA, s0, s1);
        { float lv = fminf(s0, s1); bool m = lv < bestA;
          bestA = fminf(bestA, lv); if (m) bjA = j; }
        unpack2(sB, s0, s1);
        { float lv = fminf(s0, s1); bool m = lv < bestB;
          bestB = fminf(bestB, lv); if (m) bjB = j; }
        unpack2(sC, s0, s1);
        { float lv = fminf(s0, s1); bool m = lv < bestC;
          bestC = fminf(bestC, lv); if (m) bjC = j; }
        unpack2(sD, s0, s1);
        { float lv = fminf(s0, s1); bool m = lv < bestD;
          bestD = fminf(bestD, lv); if (m) bjD = j; }

        r0 = n0; r1 = n1; r2 = n2; r3 = n3; q = qn;
    }

    // ---- epilogue: recompute ONLY the winning pair per b to resolve the
    // even/odd lane. Identical op sequence => bitwise-identical scores.
    // Even lane wins ties (strict s1 < s0), matching first-index argmax.
    const u64* wsel[4] = { wa, wb, wc, wd };
    const u64  vsel[4] = { vsqA, vsqB, vsqC, vsqD };
    const int  jsel[4] = { bjA, bjB, bjC, bjD };

    #pragma unroll
    for (int g = 0; g < 4; ++g) {
        const u64* w = wsel[g];
        const int bj = jsel[g];
        ulonglong2 m0 = rows[bj * 4 + 0], m1 = rows[bj * 4 + 1];
        ulonglong2 m2 = rows[bj * 4 + 2], m3 = rows[bj * 4 + 3];
        u64 qq = nq[bj];
        u64 acc = 0ULL;
        acc = ffma2(w[0], m0.x, acc); acc = ffma2(w[1], m0.y, acc);
        acc = ffma2(w[2], m1.x, acc); acc = ffma2(w[3], m1.y, acc);
        acc = ffma2(w[4], m2.x, acc); acc = ffma2(w[5], m2.y, acc);
        acc = ffma2(w[6], m3.x, acc); acc = ffma2(w[7], m3.y, acc);
        u64 s = fadd2(ffma2(acc, NEG2, vsel[g]), qq);
        float s0, s1; unpack2(s, s0, s1);
        int lane = (s1 < s0) ? 1 : 0;
        int base = bj * 16 + lane;

        float4 o0 = make_float4(cbi[base],      cbi[base + 2],
                                cbi[base + 4],  cbi[base + 6]);
        float4 o1 = make_float4(cbi[base + 8],  cbi[base + 10],
                                cbi[base + 12], cbi[base + 14]);
        float4* o = (float4*)(out + (size_t)(b0 + g * 64) * DN + p * SDN);
        o[0] = o0; o[1] = o1;
    }
}

extern "C" void kernel_launch(void* const* d_in, const int* in_sizes, int n_in,
                              void* d_out, int out_size) {
    const float* vecs     = (const float*)d_in[0];
    const float* codebook = (const float*)d_in[1];
    // Defensive: inputs are (vecs: B*D = 3145728, codebook: P*C*SD = 196608)
    if (n_in >= 2 && in_sizes[0] == PN * CN * SDN && in_sizes[1] == BN * DN) {
        const float* tmp = vecs; vecs = codebook; codebook = tmp;
    }
    float* out = (float*)d_out;
    dim3 grid(BN / 256, PN);
    pq_argmax_kernel<<<grid, 64>>>(vecs, codebook, out);
}

// round 15
// speedup vs baseline: 1.4433x; 1.0396x over previous
#include <cuda_runtime.h>

#define BN 4096
#define DN 768
#define PN 96
#define CN 256
#define SDN 8

typedef unsigned long long u64;

__device__ __forceinline__ u64 ffma2(u64 a, u64 b, u64 c) {
    u64 d;
    asm("fma.rn.f32x2 %0, %1, %2, %3;" : "=l"(d) : "l"(a), "l"(b), "l"(c));
    return d;
}
__device__ __forceinline__ u64 fadd2(u64 a, u64 b) {
    u64 d;
    asm("add.rn.f32x2 %0, %1, %2;" : "=l"(d) : "l"(a), "l"(b));
    return d;
}
__device__ __forceinline__ u64 pack2(float lo, float hi) {
    u64 r;
    asm("mov.b64 %0, {%1, %2};" : "=l"(r) : "f"(lo), "f"(hi));
    return r;
}
__device__ __forceinline__ void unpack2(u64 v, float& lo, float& hi) {
    asm("mov.b64 {%0, %1}, %2;" : "=f"(lo), "=f"(hi) : "l"(v));
}

// v_sq / c_sq with the reference's rounding: elementwise square (rn), then
// strictly sequential adds (rn), no fma contraction.
__device__ __forceinline__ float sumsq8(float4 lo, float4 hi) {
    float q = __fmul_rn(lo.x, lo.x);
    q = __fadd_rn(q, __fmul_rn(lo.y, lo.y));
    q = __fadd_rn(q, __fmul_rn(lo.z, lo.z));
    q = __fadd_rn(q, __fmul_rn(lo.w, lo.w));
    q = __fadd_rn(q, __fmul_rn(hi.x, hi.x));
    q = __fadd_rn(q, __fmul_rn(hi.y, hi.y));
    q = __fadd_rn(q, __fmul_rn(hi.z, hi.z));
    q = __fadd_rn(q, __fmul_rn(hi.w, hi.w));
    return q;
}

// Block: 128 threads, 2 batch vectors per thread (256 b/block), one partition.
// Grid: (BN/256 = 16, PN = 96) = 1536 blocks. __launch_bounds__(128, 11):
// 11 blocks/SM -> chip capacity 1628 >= 1536 -> single wave, no tail.
__global__ __launch_bounds__(128, 11) void pq_argmax_kernel(
    const float* __restrict__ vecs,
    const float* __restrict__ codebook,
    float* __restrict__ out)
{
    // Pair-interleaved codebook: row j (16 floats) = {c0_d0,c1_d0,c0_d1,c1_d1,...}
    // where c0 = 2j, c1 = 2j+1. One LDS.128 yields two packed f32x2 operands.
    __shared__ __align__(16) float cbi[CN * SDN];
    __shared__ __align__(8)  float csq[CN];   // +||c||^2, natural c order

    const int t = threadIdx.x;
    const int p = blockIdx.y;
    const float* cb = codebook + (size_t)p * CN * SDN;

    // ---- issue the two sub-vector loads FIRST (overlap LDG latency with
    // codebook staging below) ----
    const int b0 = blockIdx.x * 256 + t;
    const int b1 = b0 + 128;
    const float4* va4 = (const float4*)(vecs + (size_t)b0 * DN + p * SDN);
    const float4* vb4 = (const float4*)(vecs + (size_t)b1 * DN + p * SDN);
    float4 a0 = va4[0], a1 = va4[1];
    float4 e0 = vb4[0], e1 = vb4[1];

    // ---- init: thread t stages centroid pair (2t, 2t+1) ----
    {
        const float4* cb4 = (const float4*)cb + t * 4;
        float4 c0lo = cb4[0], c0hi = cb4[1];   // centroid 2t,   dims 0-3 / 4-7
        float4 c1lo = cb4[2], c1hi = cb4[3];   // centroid 2t+1

        float4* row = (float4*)(cbi + t * 16);
        row[0] = make_float4(c0lo.x, c1lo.x, c0lo.y, c1lo.y);
        row[1] = make_float4(c0lo.z, c1lo.z, c0lo.w, c1lo.w);
        row[2] = make_float4(c0hi.x, c1hi.x, c0hi.y, c1hi.y);
        row[3] = make_float4(c0hi.z, c1hi.z, c0hi.w, c1hi.w);
        csq[2 * t]     = sumsq8(c0lo, c0hi);
        csq[2 * t + 1] = sumsq8(c1lo, c1hi);
    }

    u64 wa[8], wb[8];
    wa[0] = pack2(a0.x, a0.x); wa[1] = pack2(a0.y, a0.y);
    wa[2] = pack2(a0.z, a0.z); wa[3] = pack2(a0.w, a0.w);
    wa[4] = pack2(a1.x, a1.x); wa[5] = pack2(a1.y, a1.y);
    wa[6] = pack2(a1.z, a1.z); wa[7] = pack2(a1.w, a1.w);
    wb[0] = pack2(e0.x, e0.x); wb[1] = pack2(e0.y, e0.y);
    wb[2] = pack2(e0.z, e0.z); wb[3] = pack2(e0.w, e0.w);
    wb[4] = pack2(e1.x, e1.x); wb[5] = pack2(e1.y, e1.y);
    wb[6] = pack2(e1.z, e1.z); wb[7] = pack2(e1.w, e1.w);

    const float vsA = sumsq8(a0, a1);
    const float vsB = sumsq8(e0, e1);
    const u64 vsqA = pack2(vsA, vsA);
    const u64 vsqB = pack2(vsB, vsB);

    __syncthreads();

    // 2*vc is exact in fp32 (exponent bump), so the reference's
    //   m = rn(2*vc); d = rn(v_sq - m)
    // equals the single fma  d = rn(v_sq - 2*vc) = fma(vc, -2, v_sq).
    const u64 NEG2 = pack2(-2.0f, -2.0f);
    const ulonglong2* rows = (const ulonglong2*)cbi;
    const u64* nq = (const u64*)csq;

    float bestA = 3.402823466e+38f, bestB = 3.402823466e+38f;
    int bjA = 0, bjB = 0;   // winning centroid-PAIR index; lane resolved later

    #pragma unroll 4
    for (int j = 0; j < CN / 2; ++j) {
        ulonglong2 r0 = rows[j * 4 + 0];   // d0, d1 (each u64 = {c_even, c_odd})
        ulonglong2 r1 = rows[j * 4 + 1];   // d2, d3
        ulonglong2 r2 = rows[j * 4 + 2];   // d4, d5
        ulonglong2 r3 = rows[j * 4 + 3];   // d6, d7
        u64 q = nq[j];                     // {csq_even, csq_odd}

        u64 accA = 0ULL, accB = 0ULL;      // {0.f, 0.f}
        accA = ffma2(wa[0], r0.x, accA);  accB = ffma2(wb[0], r0.x, accB);
        accA = ffma2(wa[1], r0.y, accA);  accB = ffma2(wb[1], r0.y, accB);
        accA = ffma2(wa[2], r1.x, accA);  accB = ffma2(wb[2], r1.x, accB);
        accA = ffma2(wa[3], r1.y, accA);  accB = ffma2(wb[3], r1.y, accB);
        accA = ffma2(wa[4], r2.x, accA);  accB = ffma2(wb[4], r2.x, accB);
        accA = ffma2(wa[5], r2.y, accA);  accB = ffma2(wb[5], r2.y, accB);
        accA = ffma2(wa[6], r3.x, accA);  accB = ffma2(wb[6], r3.x, accB);
        accA = ffma2(wa[7], r3.y, accA);  accB = ffma2(wb[7], r3.y, accB);

        u64 sA = fadd2(ffma2(accA, NEG2, vsqA), q);
        u64 sB = fadd2(ffma2(accB, NEG2, vsqB), q);

        float s0, s1;
        unpack2(sA, s0, s1);
        // Index-free tournament: strict '<' on the pair-min keeps the earliest
        // pair on exact ties (matches jnp.argmax first-index on proba = -s).
        { float lv = fminf(s0, s1); bool m = lv < bestA;
          bestA = fminf(bestA, lv); if (m) bjA = j; }
        unpack2(sB, s0, s1);
        { float lv = fminf(s0, s1); bool m = lv < bestB;
          bestB = fminf(bestB, lv); if (m) bjB = j; }
    }

    // ---- epilogue: recompute ONLY the winning pair to resolve even/odd lane.
    // Identical op sequence => bitwise-identical scores. Even lane wins ties
    // (strict s1 < s0), matching first-index argmax. Explicitly unrolled, no
    // indexed local arrays (those cost registers / risk spills).
    {
        ulonglong2 r0 = rows[bjA * 4 + 0], r1 = rows[bjA * 4 + 1];
        ulonglong2 r2 = rows[bjA * 4 + 2], r3 = rows[bjA * 4 + 3];
        u64 q = nq[bjA];
        u64 acc = 0ULL;
        acc = ffma2(wa[0], r0.x, acc); acc = ffma2(wa[1], r0.y, acc);
        acc = ffma2(wa[2], r1.x, acc); acc = ffma2(wa[3], r1.y, acc);
        acc = ffma2(wa[4], r2.x, acc); acc = ffma2(wa[5], r2.y, acc);
        acc = ffma2(wa[6], r3.x, acc); acc = ffma2(wa[7], r3.y, acc);
        u64 s = fadd2(ffma2(acc, NEG2, vsqA), q);
        float s0, s1; unpack2(s, s0, s1);
        int base = bjA * 16 + ((s1 < s0) ? 1 : 0);

        float4 o0 = make_float4(cbi[base],      cbi[base + 2],
                                cbi[base + 4],  cbi[base + 6]);
        float4 o1 = make_float4(cbi[base + 8],  cbi[base + 10],
                                cbi[base + 12], cbi[base + 14]);
        float4* o = (float4*)(out + (size_t)b0 * DN + p * SDN);
        o[0] = o0; o[1] = o1;
    }
    {
        ulonglong2 r0 = rows[bjB * 4 + 0], r1 = rows[bjB * 4 + 1];
        ulonglong2 r2 = rows[bjB * 4 + 2], r3 = rows[bjB * 4 + 3];
        u64 q = nq[bjB];
        u64 acc = 0ULL;
        acc = ffma2(wb[0], r0.x, acc); acc = ffma2(wb[1], r0.y, acc);
        acc = ffma2(wb[2], r1.x, acc); acc = ffma2(wb[3], r1.y, acc);
        acc = ffma2(wb[4], r2.x, acc); acc = ffma2(wb[5], r2.y, acc);
        acc = ffma2(wb[6], r3.x, acc); acc = ffma2(wb[7], r3.y, acc);
        u64 s = fadd2(ffma2(acc, NEG2, vsqB), q);
        float s0, s1; unpack2(s, s0, s1);
        int base = bjB * 16 + ((s1 < s0) ? 1 : 0);

        float4 o0 = make_float4(cbi[base],      cbi[base + 2],
                                cbi[base + 4],  cbi[base + 6]);
        float4 o1 = make_float4(cbi[base + 8],  cbi[base + 10],
                                cbi[base + 12], cbi[base + 14]);
        float4* o = (float4*)(out + (size_t)b1 * DN + p * SDN);
        o[0] = o0; o[1] = o1;
    }
}

extern "C" void kernel_launch(void* const* d_in, const int* in_sizes, int n_in,
                              void* d_out, int out_size) {
    const float* vecs     = (const float*)d_in[0];
    const float* codebook = (const float*)d_in[1];
    // Defensive: inputs are (vecs: B*D = 3145728, codebook: P*C*SD = 196608)
    if (n_in >= 2 && in_sizes[0] == PN * CN * SDN && in_sizes[1] == BN * DN) {
        const float* tmp = vecs; vecs = codebook; codebook = tmp;
    }
    float* out = (float*)d_out;
    dim3 grid(BN / 256, PN);
    pq_argmax_kernel<<<grid, 128>>>(vecs, codebook, out);
}